// round 15
// baseline (speedup 1.0000x reference)
#include <cuda_runtime.h>
#include <math.h>

#define Bdim 4
#define Ndim 48
#define Rdim 16
#define Tdim 33
#define NCdim 80
#define NIdim 5
#define NN (Ndim * Ndim)          // 2304
#define NEGV -1000.0f
#define PREP_ROWS 32
#define PITCH 49                  // conflict-free row-major pitch

// g_M[b,t][u*48+v] = trans[b,u,v,t]
__device__ float g_M[Bdim * Tdim * NN];

// ---------------------------------------------------------------------------
// Kernel 0: streaming transpose [B*2304, 33] -> per-t rows, PLUS output init:
// out[b,xy,t] = (mask==0) ? bias[t] : NEG.  dp then atomically accumulates.
__global__ __launch_bounds__(256) void prep_kernel(const float* __restrict__ trans,
                                                   const int*   __restrict__ type_mask,
                                                   const float* __restrict__ biases,
                                                   float*       __restrict__ out)
{
    __shared__ float tile[PREP_ROWS * Tdim];   // 1056 floats

    const int chunk = blockIdx.x;              // 0..71
    const int b     = blockIdx.y;
    const int tid   = threadIdx.x;
    const int row0  = chunk * PREP_ROWS;

    const float* src = trans + ((size_t)b * NN + row0) * Tdim;
    #pragma unroll
    for (int i = tid; i < PREP_ROWS * Tdim; i += 256)
        tile[i] = __ldg(src + i);              // fully coalesced
    __syncthreads();

    float* dst = g_M + (size_t)b * Tdim * NN + row0;
    #pragma unroll
    for (int i = tid; i < PREP_ROWS * Tdim; i += 256) {
        const int t = i >> 5;                  // /32
        const int r = i & 31;
        dst[(size_t)t * NN + r] = tile[r * Tdim + t];   // stride-33 smem: conflict-free
    }

    // ---- output init: 2 coalesced elements per thread ----
    const int gidx = (b * gridDim.x + chunk) * 256 + tid;   // 0..73727
    #pragma unroll
    for (int h = 0; h < 2; h++) {
        const int idx = gidx + h * 73728;      // covers 147456 = B*NN*R
        const int t = idx & 15;
        out[idx] = (__ldg(type_mask + idx) == 0) ? __ldg(biases + t) : NEGV;
    }
}

// ---------------------------------------------------------------------------
// Kernel 1: one CTA per (c, b). 288 threads: thread = (oct, xr), oct=tid/48
// (column octet, warp-broadcast B reads), xr=tid%48 (row, conflict-free
// pitch-49 A reads). 8 outputs/thread. Epilogue: masked atomic accumulate of
// weights[c]*exp(score) directly into out (combine fused, no scratch).
__global__ __launch_bounds__(288) void dp_kernel(const int*   __restrict__ rules,
                                                 const int*   __restrict__ type_mask,
                                                 const float* __restrict__ weights,
                                                 float*       __restrict__ out)
{
    __shared__ float A0[Ndim * PITCH];         // hop0 (pitch 49), then S
    __shared__ float B1[NN];                   // hop1
    __shared__ float B2[NN];                   // hop2

    const int c = blockIdx.x;
    const int b = blockIdx.y;
    const int t = c / NIdim;

    const int tid = threadIdx.x;
    const int oct = tid / Ndim;                // 0..5
    const int xr  = tid - oct * Ndim;          // 0..47

    const int r0 = __ldg(rules + c * 3 + 0);
    const int r1 = __ldg(rules + c * 3 + 1);
    const int r2 = __ldg(rules + c * 3 + 2);
    const float wc = __ldg(weights + c);       // weights is [16,5] row-major == flat [c]

    const float*  h0 = g_M + (size_t)(b * Tdim + r0) * NN;
    const float4* h1 = (const float4*)(g_M + (size_t)(b * Tdim + r1) * NN);
    const float4* h2 = (const float4*)(g_M + (size_t)(b * Tdim + r2) * NN);

    float4* B14 = (float4*)B1;
    float4* B24 = (float4*)B2;
    #pragma unroll
    for (int j = 0; j < 2; j++) {
        B14[tid + j * 288] = h1[tid + j * 288];
        B24[tid + j * 288] = h2[tid + j * 288];
    }
    #pragma unroll
    for (int i = tid; i < NN; i += 288) {
        const int u = i / Ndim;
        const int v = i - u * Ndim;
        A0[u * PITCH + v] = h0[i];             // coalesced gmem read
    }
    __syncthreads();

    float a0, a1, a2, a3, a4, a5, a6, a7;
    a0 = a1 = a2 = a3 = a4 = a5 = a6 = a7 = -INFINITY;

    const float* ap  = A0 + xr * PITCH;
    const float* bp1 = B1 + oct * 8;

    // ---- stage 1: S[x][oct*8..+7] = max_k hop0[x][k] + hop1[k][..] ----
    #pragma unroll 8
    for (int k = 0; k < Ndim; k++) {
        const float  av  = ap[k];                              // conflict-free
        const float4 bv0 = *(const float4*)(bp1 + k * Ndim);   // warp-broadcast
        const float4 bv1 = *(const float4*)(bp1 + k * Ndim + 4);
        a0 = fmaxf(a0, av + bv0.x); a1 = fmaxf(a1, av + bv0.y);
        a2 = fmaxf(a2, av + bv0.z); a3 = fmaxf(a3, av + bv0.w);
        a4 = fmaxf(a4, av + bv1.x); a5 = fmaxf(a5, av + bv1.y);
        a6 = fmaxf(a6, av + bv1.z); a7 = fmaxf(a7, av + bv1.w);
    }
    __syncthreads();                           // all A0 reads done

    // write S into A0 (same pitch-49 layout, disjoint per thread)
    {
        float* sp = A0 + xr * PITCH + oct * 8;
        sp[0] = a0; sp[1] = a1; sp[2] = a2; sp[3] = a3;
        sp[4] = a4; sp[5] = a5; sp[6] = a6; sp[7] = a7;
    }
    __syncthreads();

    // ---- stage 2: score[x][oct*8..+7] = max_k S[x][k] + hop2[k][..] ----
    a0 = a1 = a2 = a3 = a4 = a5 = a6 = a7 = -INFINITY;
    const float* bp2 = B2 + oct * 8;

    #pragma unroll 8
    for (int k = 0; k < Ndim; k++) {
        const float  av  = ap[k];                              // S row, conflict-free
        const float4 bv0 = *(const float4*)(bp2 + k * Ndim);   // warp-broadcast
        const float4 bv1 = *(const float4*)(bp2 + k * Ndim + 4);
        a0 = fmaxf(a0, av + bv0.x); a1 = fmaxf(a1, av + bv0.y);
        a2 = fmaxf(a2, av + bv0.z); a3 = fmaxf(a3, av + bv0.w);
        a4 = fmaxf(a4, av + bv1.x); a5 = fmaxf(a5, av + bv1.y);
        a6 = fmaxf(a6, av + bv1.z); a7 = fmaxf(a7, av + bv1.w);
    }

    // ---- fused combine: masked atomic accumulate into out[b,xy,t] ----
    {
        const int base = ((b * NN + xr * Ndim + oct * 8) << 4) + t;  // idx of j=0
        float sc[8] = {a0, a1, a2, a3, a4, a5, a6, a7};
        #pragma unroll
        for (int j = 0; j < 8; j++) {
            const int oidx = base + (j << 4);                 // y-step => +16
            if (__ldg(type_mask + oidx) == 0)
                atomicAdd(out + oidx, wc * __expf(sc[j]));    // REDG, spread addrs
        }
    }
}

extern "C" void kernel_launch(void* const* d_in, const int* in_sizes, int n_in,
                              void* d_out, int out_size)
{
    const float* transitions = (const float*)d_in[0];
    const int*   type_mask   = (const int*)  d_in[1];
    const int*   rules       = (const int*)  d_in[2];
    const float* weights     = (const float*)d_in[3];
    const float* biases      = (const float*)d_in[4];
    float* out = (float*)d_out;

    dim3 grid0(NN / PREP_ROWS, Bdim);          // (72, 4) = 288 CTAs
    prep_kernel<<<grid0, 256>>>(transitions, type_mask, biases, out);

    dim3 grid1(NCdim, Bdim);                   // (80, 4) = 320 CTAs
    dp_kernel<<<grid1, 288>>>(rules, type_mask, weights, out);
}

// round 16
// speedup vs baseline: 1.0158x; 1.0158x over previous
#include <cuda_runtime.h>
#include <math.h>

#define Bdim 4
#define Ndim 48
#define Rdim 16
#define Tdim 33
#define NCdim 80
#define NIdim 5
#define NN (Ndim * Ndim)          // 2304
#define NEGV -1000.0f
#define PREP_ROWS 32
#define HROWS 24                  // rows per dp CTA (z-split)
#define PITCH 49                  // conflict-free row-major pitch

// g_M[b,t][u*48+v] = trans[b,u,v,t]
__device__ float g_M[Bdim * Tdim * NN];

// ---------------------------------------------------------------------------
// Kernel 0: streaming transpose [B*2304, 33] -> per-t rows, PLUS output init:
// out[b,xy,t] = (mask==0) ? bias[t] : NEG.  dp then atomically accumulates.
__global__ __launch_bounds__(256) void prep_kernel(const float* __restrict__ trans,
                                                   const int*   __restrict__ type_mask,
                                                   const float* __restrict__ biases,
                                                   float*       __restrict__ out)
{
    __shared__ float tile[PREP_ROWS * Tdim];   // 1056 floats

    const int chunk = blockIdx.x;              // 0..71
    const int b     = blockIdx.y;
    const int tid   = threadIdx.x;
    const int row0  = chunk * PREP_ROWS;

    const float* src = trans + ((size_t)b * NN + row0) * Tdim;
    #pragma unroll
    for (int i = tid; i < PREP_ROWS * Tdim; i += 256)
        tile[i] = __ldg(src + i);              // fully coalesced
    __syncthreads();

    float* dst = g_M + (size_t)b * Tdim * NN + row0;
    #pragma unroll
    for (int i = tid; i < PREP_ROWS * Tdim; i += 256) {
        const int t = i >> 5;                  // /32
        const int r = i & 31;
        dst[(size_t)t * NN + r] = tile[r * Tdim + t];   // stride-33 smem: conflict-free
    }

    // ---- output init: 2 coalesced elements per thread ----
    const int gidx = (b * gridDim.x + chunk) * 256 + tid;   // 0..73727
    #pragma unroll
    for (int h = 0; h < 2; h++) {
        const int idx = gidx + h * 73728;      // covers 147456 = B*NN*R
        const int t = idx & 15;
        out[idx] = (__ldg(type_mask + idx) == 0) ? __ldg(biases + t) : NEGV;
    }
}

// ---------------------------------------------------------------------------
// Kernel 1: one CTA per (c, b, row-half) — the measured-best R10 shape.
// 144 threads: thread = (oct, xr), oct = column octet (0..5, warp-broadcast B
// reads), xr = local row (0..23, conflict-free pitch-49 A reads). 8 outputs
// per thread. Epilogue: masked atomic accumulate of weights[c]*exp(score)
// directly into out (combine fused, no scratch).
__global__ __launch_bounds__(144) void dp_kernel(const int*   __restrict__ rules,
                                                 const int*   __restrict__ type_mask,
                                                 const float* __restrict__ weights,
                                                 float*       __restrict__ out)
{
    __shared__ float A0[HROWS * PITCH];        // hop0 slice (pitch 49), then S
    __shared__ float B1[NN];                   // hop1 (full)
    __shared__ float B2[NN];                   // hop2 (full)

    const int c = blockIdx.x;
    const int b = blockIdx.y;
    const int rowbase = blockIdx.z * HROWS;
    const int t = c / NIdim;

    const int tid = threadIdx.x;
    const int oct = tid / HROWS;               // 0..5
    const int xr  = tid - oct * HROWS;         // 0..23

    const int r0 = __ldg(rules + c * 3 + 0);
    const int r1 = __ldg(rules + c * 3 + 1);
    const int r2 = __ldg(rules + c * 3 + 2);
    const float wc = __ldg(weights + c);       // weights [16,5] row-major == flat [c]

    const float*  h0 = g_M + (size_t)(b * Tdim + r0) * NN + rowbase * Ndim;
    const float4* h1 = (const float4*)(g_M + (size_t)(b * Tdim + r1) * NN);
    const float4* h2 = (const float4*)(g_M + (size_t)(b * Tdim + r2) * NN);

    float4* B14 = (float4*)B1;
    float4* B24 = (float4*)B2;
    #pragma unroll
    for (int j = 0; j < 4; j++) {
        B14[tid + j * 144] = h1[tid + j * 144];
        B24[tid + j * 144] = h2[tid + j * 144];
    }
    #pragma unroll
    for (int i = tid; i < HROWS * Ndim; i += 144) {
        const int u = i / Ndim;
        const int v = i - u * Ndim;
        A0[u * PITCH + v] = h0[i];             // coalesced gmem read
    }
    __syncthreads();

    float a0, a1, a2, a3, a4, a5, a6, a7;
    a0 = a1 = a2 = a3 = a4 = a5 = a6 = a7 = -INFINITY;

    const float* ap  = A0 + xr * PITCH;
    const float* bp1 = B1 + oct * 8;

    // ---- stage 1: S[x][oct*8..+7] = max_k hop0[x][k] + hop1[k][..] ----
    #pragma unroll 8
    for (int k = 0; k < Ndim; k++) {
        const float  av  = ap[k];                              // conflict-free
        const float4 bv0 = *(const float4*)(bp1 + k * Ndim);   // warp-broadcast
        const float4 bv1 = *(const float4*)(bp1 + k * Ndim + 4);
        a0 = fmaxf(a0, av + bv0.x); a1 = fmaxf(a1, av + bv0.y);
        a2 = fmaxf(a2, av + bv0.z); a3 = fmaxf(a3, av + bv0.w);
        a4 = fmaxf(a4, av + bv1.x); a5 = fmaxf(a5, av + bv1.y);
        a6 = fmaxf(a6, av + bv1.z); a7 = fmaxf(a7, av + bv1.w);
    }
    __syncthreads();                           // all A0 reads done

    // write S into A0 (same pitch-49 layout, disjoint per thread)
    {
        float* sp = A0 + xr * PITCH + oct * 8;
        sp[0] = a0; sp[1] = a1; sp[2] = a2; sp[3] = a3;
        sp[4] = a4; sp[5] = a5; sp[6] = a6; sp[7] = a7;
    }
    __syncthreads();

    // ---- stage 2: score[x][oct*8..+7] = max_k S[x][k] + hop2[k][..] ----
    a0 = a1 = a2 = a3 = a4 = a5 = a6 = a7 = -INFINITY;
    const float* bp2 = B2 + oct * 8;

    #pragma unroll 8
    for (int k = 0; k < Ndim; k++) {
        const float  av  = ap[k];                              // S row, conflict-free
        const float4 bv0 = *(const float4*)(bp2 + k * Ndim);   // warp-broadcast
        const float4 bv1 = *(const float4*)(bp2 + k * Ndim + 4);
        a0 = fmaxf(a0, av + bv0.x); a1 = fmaxf(a1, av + bv0.y);
        a2 = fmaxf(a2, av + bv0.z); a3 = fmaxf(a3, av + bv0.w);
        a4 = fmaxf(a4, av + bv1.x); a5 = fmaxf(a5, av + bv1.y);
        a6 = fmaxf(a6, av + bv1.z); a7 = fmaxf(a7, av + bv1.w);
    }

    // ---- fused combine: masked atomic accumulate into out[b,xy,t] ----
    {
        const int base = ((b * NN + (rowbase + xr) * Ndim + oct * 8) << 4) + t;
        float sc[8] = {a0, a1, a2, a3, a4, a5, a6, a7};
        #pragma unroll
        for (int j = 0; j < 8; j++) {
            const int oidx = base + (j << 4);                 // y-step => +16
            if (__ldg(type_mask + oidx) == 0)
                atomicAdd(out + oidx, wc * __expf(sc[j]));    // REDG, spread addrs
        }
    }
}

extern "C" void kernel_launch(void* const* d_in, const int* in_sizes, int n_in,
                              void* d_out, int out_size)
{
    const float* transitions = (const float*)d_in[0];
    const int*   type_mask   = (const int*)  d_in[1];
    const int*   rules       = (const int*)  d_in[2];
    const float* weights     = (const float*)d_in[3];
    const float* biases      = (const float*)d_in[4];
    float* out = (float*)d_out;

    dim3 grid0(NN / PREP_ROWS, Bdim);          // (72, 4) = 288 CTAs
    prep_kernel<<<grid0, 256>>>(transitions, type_mask, biases, out);

    dim3 grid1(NCdim, Bdim, Ndim / HROWS);     // (80, 4, 2) = 640 CTAs
    dp_kernel<<<grid1, 144>>>(rules, type_mask, weights, out);
}

// round 17
// speedup vs baseline: 1.1786x; 1.1603x over previous
#include <cuda_runtime.h>
#include <math.h>

#define Bdim 4
#define Ndim 48
#define Rdim 16
#define Tdim 33
#define NCdim 80
#define NIdim 5
#define NN (Ndim * Ndim)          // 2304
#define NEGV -1000.0f
#define PREP_ROWS 64
#define HROWS 24                  // rows per dp CTA (z-split)
#define PITCH 49                  // conflict-free row-major pitch
#define XCH 64                    // xy chunk per combine CTA

// g_M[b,t][u*48+v] = trans[b,u,v,t]
__device__ float g_M[Bdim * Tdim * NN];
// scratch: exp(path score) per [b, c, xy]
__device__ float g_scratch[Bdim * NCdim * NN];

// ---------------------------------------------------------------------------
// Kernel 0: streaming transpose [B*2304, 33] -> per-t rows. float4 both sides.
__global__ __launch_bounds__(256) void prep_kernel(const float* __restrict__ trans)
{
    __shared__ float tile[PREP_ROWS * Tdim];   // 2112 floats (= 528 float4)

    const int chunk = blockIdx.x;              // 0..35
    const int b     = blockIdx.y;
    const int tid   = threadIdx.x;
    const int row0  = chunk * PREP_ROWS;

    // flat-contiguous float4 loads (64*33 floats)
    const float4* src4 = (const float4*)(trans + ((size_t)b * NN + row0) * Tdim);
    float4* tile4 = (float4*)tile;
    #pragma unroll
    for (int i = tid; i < PREP_ROWS * Tdim / 4; i += 256)
        tile4[i] = __ldg(src4 + i);
    __syncthreads();

    // float4 stores: per t, 16 float4 (64 consecutive r)
    #pragma unroll
    for (int i = tid; i < Tdim * (PREP_ROWS / 4); i += 256) {
        const int t = i >> 4;                  // /16
        const int q = i & 15;
        const int r = q * 4;
        float4 v = make_float4(tile[(r + 0) * Tdim + t],
                               tile[(r + 1) * Tdim + t],
                               tile[(r + 2) * Tdim + t],
                               tile[(r + 3) * Tdim + t]);   // stride-33: conflict-free
        float4* dst4 = (float4*)(g_M + (size_t)(b * Tdim + t) * NN + row0);
        dst4[q] = v;
    }
}

// ---------------------------------------------------------------------------
// Kernel 1: one CTA per (c, b, row-half). 144 threads: thread = (oct, xr),
// oct = column octet (warp-broadcast B reads), xr = local row (conflict-free
// pitch-49 A reads). 8 outputs per thread; coalesced float4 scratch stores.
__global__ __launch_bounds__(144) void dp_kernel(const int* __restrict__ rules)
{
    __shared__ float A0[HROWS * PITCH];        // hop0 slice (pitch 49), then S
    __shared__ float B1[NN];                   // hop1 (full)
    __shared__ float B2[NN];                   // hop2 (full)

    const int c = blockIdx.x;
    const int b = blockIdx.y;
    const int rowbase = blockIdx.z * HROWS;

    const int tid = threadIdx.x;
    const int oct = tid / HROWS;               // 0..5
    const int xr  = tid - oct * HROWS;         // 0..23

    const int r0 = __ldg(rules + c * 3 + 0);
    const int r1 = __ldg(rules + c * 3 + 1);
    const int r2 = __ldg(rules + c * 3 + 2);

    const float*  h0 = g_M + (size_t)(b * Tdim + r0) * NN + rowbase * Ndim;
    const float4* h1 = (const float4*)(g_M + (size_t)(b * Tdim + r1) * NN);
    const float4* h2 = (const float4*)(g_M + (size_t)(b * Tdim + r2) * NN);

    float4* B14 = (float4*)B1;
    float4* B24 = (float4*)B2;
    #pragma unroll
    for (int j = 0; j < 4; j++) {
        B14[tid + j * 144] = h1[tid + j * 144];
        B24[tid + j * 144] = h2[tid + j * 144];
    }
    #pragma unroll
    for (int i = tid; i < HROWS * Ndim; i += 144) {
        const int u = i / Ndim;
        const int v = i - u * Ndim;
        A0[u * PITCH + v] = h0[i];             // coalesced gmem read
    }
    __syncthreads();

    float a0, a1, a2, a3, a4, a5, a6, a7;
    a0 = a1 = a2 = a3 = a4 = a5 = a6 = a7 = -INFINITY;

    const float* ap  = A0 + xr * PITCH;
    const float* bp1 = B1 + oct * 8;

    // ---- stage 1: S[x][oct*8..+7] = max_k hop0[x][k] + hop1[k][..] ----
    #pragma unroll 8
    for (int k = 0; k < Ndim; k++) {
        const float  av  = ap[k];                              // conflict-free
        const float4 bv0 = *(const float4*)(bp1 + k * Ndim);   // warp-broadcast
        const float4 bv1 = *(const float4*)(bp1 + k * Ndim + 4);
        a0 = fmaxf(a0, av + bv0.x); a1 = fmaxf(a1, av + bv0.y);
        a2 = fmaxf(a2, av + bv0.z); a3 = fmaxf(a3, av + bv0.w);
        a4 = fmaxf(a4, av + bv1.x); a5 = fmaxf(a5, av + bv1.y);
        a6 = fmaxf(a6, av + bv1.z); a7 = fmaxf(a7, av + bv1.w);
    }
    __syncthreads();                           // all A0 reads done

    // write S into A0 (same pitch-49 layout, disjoint per thread)
    {
        float* sp = A0 + xr * PITCH + oct * 8;
        sp[0] = a0; sp[1] = a1; sp[2] = a2; sp[3] = a3;
        sp[4] = a4; sp[5] = a5; sp[6] = a6; sp[7] = a7;
    }
    __syncthreads();

    // ---- stage 2: out = exp( max_k S[x][k] + hop2[k][..] ) ----
    a0 = a1 = a2 = a3 = a4 = a5 = a6 = a7 = -INFINITY;
    const float* bp2 = B2 + oct * 8;

    #pragma unroll 8
    for (int k = 0; k < Ndim; k++) {
        const float  av  = ap[k];                              // S row, conflict-free
        const float4 bv0 = *(const float4*)(bp2 + k * Ndim);   // warp-broadcast
        const float4 bv1 = *(const float4*)(bp2 + k * Ndim + 4);
        a0 = fmaxf(a0, av + bv0.x); a1 = fmaxf(a1, av + bv0.y);
        a2 = fmaxf(a2, av + bv0.z); a3 = fmaxf(a3, av + bv0.w);
        a4 = fmaxf(a4, av + bv1.x); a5 = fmaxf(a5, av + bv1.y);
        a6 = fmaxf(a6, av + bv1.z); a7 = fmaxf(a7, av + bv1.w);
    }

    float* op = g_scratch + ((size_t)b * NCdim + c) * NN + (rowbase + xr) * Ndim + oct * 8;
    *(float4*)(op + 0) = make_float4(__expf(a0), __expf(a1), __expf(a2), __expf(a3));
    *(float4*)(op + 4) = make_float4(__expf(a4), __expf(a5), __expf(a6), __expf(a7));
}

// ---------------------------------------------------------------------------
// Kernel 2: CTA per (64-xy chunk, b). Loads all 80 chain rows for the chunk
// fully coalesced (float4, 100% sector efficiency), computes in padded smem,
// stages outputs, writes mask/out perfectly coalesced.
__global__ __launch_bounds__(256) void combine_kernel(const int*   __restrict__ type_mask,
                                                      const float* __restrict__ weights,
                                                      const float* __restrict__ biases,
                                                      float*       __restrict__ out)
{
    __shared__ float Sc[NCdim * 65];           // [c][xyl], pitch 65 (20.8 KB)
    __shared__ float So[XCH * 17];             // [xyl][t], pitch 17 (4.4 KB)
    __shared__ float ws[NCdim];
    __shared__ float bs[Rdim];

    const int chunk = blockIdx.x;              // 0..35
    const int b     = blockIdx.y;
    const int tid   = threadIdx.x;
    const int xy0   = chunk * XCH;

    if (tid < NCdim) ws[tid] = __ldg(weights + tid);
    if (tid < Rdim)  bs[tid] = __ldg(biases + tid);

    // load: 80 chains x 16 float4 (fully coalesced; 5 iters, MLP 5)
    const float4* sc4 = (const float4*)g_scratch;
    #pragma unroll
    for (int i = tid; i < NCdim * (XCH / 4); i += 256) {
        const int c = i >> 4;                  // /16
        const int q = i & 15;
        const float4 v = __ldg(sc4 + (size_t)(b * NCdim + c) * (NN / 4) + (xy0 >> 2) + q);
        float* s = Sc + c * 65 + q * 4;
        s[0] = v.x; s[1] = v.y; s[2] = v.z; s[3] = v.w;
    }
    __syncthreads();

    // compute: thread = (tgroup, xyl); 4 t's per thread, conflict-free reads
    {
        const int tg  = tid >> 6;              // 0..3
        const int xyl = tid & 63;
        #pragma unroll
        for (int q = 0; q < 4; q++) {
            const int t = tg * 4 + q;
            float acc = bs[t];
            #pragma unroll
            for (int i = 0; i < NIdim; i++)
                acc = fmaf(Sc[(t * NIdim + i) * 65 + xyl], ws[t * NIdim + i], acc);
            So[xyl * 17 + t] = acc;
        }
    }
    __syncthreads();

    // write: 1024 outputs = 256 float4, coalesced mask + out
    {
        const int i = tid;                     // 0..255
        const int xyl = i >> 2;
        const int tq  = (i & 3) * 4;
        const float* s = So + xyl * 17 + tq;
        const int4 m = __ldg((const int4*)(type_mask + (size_t)(b * NN + xy0) * Rdim) + i);
        float4 o;
        o.x = (m.x == 0) ? s[0] : NEGV;
        o.y = (m.y == 0) ? s[1] : NEGV;
        o.z = (m.z == 0) ? s[2] : NEGV;
        o.w = (m.w == 0) ? s[3] : NEGV;
        ((float4*)(out + (size_t)(b * NN + xy0) * Rdim))[i] = o;
    }
}

extern "C" void kernel_launch(void* const* d_in, const int* in_sizes, int n_in,
                              void* d_out, int out_size)
{
    const float* transitions = (const float*)d_in[0];
    const int*   type_mask   = (const int*)  d_in[1];
    const int*   rules       = (const int*)  d_in[2];
    const float* weights     = (const float*)d_in[3];
    const float* biases      = (const float*)d_in[4];
    float* out = (float*)d_out;

    dim3 grid0(NN / PREP_ROWS, Bdim);          // (36, 4) = 144 CTAs
    prep_kernel<<<grid0, 256>>>(transitions);

    dim3 grid1(NCdim, Bdim, Ndim / HROWS);     // (80, 4, 2) = 640 CTAs
    dp_kernel<<<grid1, 144>>>(rules);

    dim3 grid2(NN / XCH, Bdim);                // (36, 4) = 144 CTAs
    combine_kernel<<<grid2, 256>>>(type_mask, weights, biases, out);
}